// round 5
// baseline (speedup 1.0000x reference)
#include <cuda_runtime.h>
#include <cuda_fp16.h>
#include <cstdint>
#include <math.h>

// Problem constants
#define D_MODEL 1024
#define NHEADS  16
#define DK      64
#define BATCH   2048
#define SEQ     20
#define M_TOTAL (BATCH * SEQ)   // 40960

// ---------------------------------------------------------------------------
// Scratch (fp16 everywhere)
// ---------------------------------------------------------------------------
__device__ __half g_xh[(size_t)M_TOTAL * D_MODEL];
__device__ __half g_wh[3][(size_t)D_MODEL * D_MODEL];
__device__ __half g_qh[(size_t)M_TOTAL * D_MODEL];
__device__ __half g_kh[(size_t)M_TOTAL * D_MODEL];
__device__ __half g_vh[(size_t)M_TOTAL * D_MODEL];

// ---------------------------------------------------------------------------
// fp32 -> fp16 conversion, 4 independent float4s per thread (MLP=4)
// ---------------------------------------------------------------------------
struct alignas(8) Half4 { __half2 a, b; };

__global__ __launch_bounds__(256) void f2h_kernel(
    const float* __restrict__ src, __half* __restrict__ dst, int n4)
{
    int base = (blockIdx.x * blockDim.x + threadIdx.x) * 4;
    float4 v[4];
    #pragma unroll
    for (int u = 0; u < 4; u++) {
        int i = base + u;
        if (i < n4) v[u] = ((const float4*)src)[i];
    }
    #pragma unroll
    for (int u = 0; u < 4; u++) {
        int i = base + u;
        if (i < n4) {
            Half4 h;
            h.a = __floats2half2_rn(v[u].x, v[u].y);
            h.b = __floats2half2_rn(v[u].z, v[u].w);
            ((Half4*)dst)[i] = h;
        }
    }
}

// ---------------------------------------------------------------------------
// fp16 m16n8k16 MMA, fp16 accumulate (chained), plus zero-C variant
// ---------------------------------------------------------------------------
__device__ __forceinline__ void mma16h_z(uint32_t* d, const uint32_t* a, const uint32_t* b) {
    asm volatile(
        "mma.sync.aligned.m16n8k16.row.col.f16.f16.f16.f16 "
        "{%0,%1}, {%2,%3,%4,%5}, {%6,%7}, {%8,%9};"
        : "=r"(d[0]), "=r"(d[1])
        : "r"(a[0]), "r"(a[1]), "r"(a[2]), "r"(a[3]),
          "r"(b[0]), "r"(b[1]), "r"(0u), "r"(0u));
}
__device__ __forceinline__ void mma16h_a(uint32_t* d, const uint32_t* a, const uint32_t* b) {
    asm volatile(
        "mma.sync.aligned.m16n8k16.row.col.f16.f16.f16.f16 "
        "{%0,%1}, {%2,%3,%4,%5}, {%6,%7}, {%0,%1};"
        : "+r"(d[0]), "+r"(d[1])
        : "r"(a[0]), "r"(a[1]), "r"(a[2]), "r"(a[3]),
          "r"(b[0]), "r"(b[1]));
}

__device__ __forceinline__ void cp16(uint32_t saddr, const void* g) {
    asm volatile("cp.async.cg.shared.global [%0], [%1], 16;\n" :: "r"(saddr), "l"(g));
}
#define CP_COMMIT() asm volatile("cp.async.commit_group;\n" ::: "memory")
#define CP_WAIT(n)  asm volatile("cp.async.wait_group %0;\n" :: "n"(n) : "memory")

__device__ __forceinline__ uint32_t smem_u32(const void* p) {
    uint32_t a;
    asm("{ .reg .u64 t; cvta.to.shared.u64 t, %1; cvt.u32.u64 %0, t; }"
        : "=r"(a) : "l"(p));
    return a;
}

// ---------------------------------------------------------------------------
// Projection GEMM: Y = X @ W^T + b for Q/K/V.
// BM=128, BN=256. 256 threads = 8 warps (2x4), warp tile 64x64.
// fp16 accumulate within K=32 (one sub-tile), promoted to fp32 masters.
// Stage = 2 x BK32 sub-tiles (BK=64 per sync), 3 stages.
// Smem sub-tile rows use 20-word stride: (g*20 + tq + {0,4}) mod 32
// covers all 32 banks -> conflict-free fragment loads.
// ---------------------------------------------------------------------------
#define GM_BM 128
#define GM_BN 256
#define WSTRIDE 20
#define A_SUB_WORDS (GM_BM * WSTRIDE)       // 2560
#define B_SUB_WORDS (GM_BN * WSTRIDE)       // 5120
#define SUB_WORDS   (A_SUB_WORDS + B_SUB_WORDS)    // 7680
#define STAGE_WORDS (2 * SUB_WORDS)                // BK=64
#define NSTAGE 3
#define GM_SMEM_BYTES (NSTAGE * STAGE_WORDS * 4)   // 184320
#define GM_KT2 (D_MODEL / 64)               // 16

__global__ __launch_bounds__(256, 1) void proj_gemm(
    const float* __restrict__ bq, const float* __restrict__ bk, const float* __restrict__ bv)
{
    extern __shared__ uint32_t smem[];
    const uint32_t sb = smem_u32(smem);

    const int tid  = threadIdx.x;
    const int lane = tid & 31;
    const int warp = tid >> 5;
    const int wr   = warp >> 2;
    const int wc   = warp & 3;
    const int g    = lane >> 2;
    const int tq   = lane & 3;

    const int proj  = blockIdx.x >> 2;
    const int nBase = (blockIdx.x & 3) * GM_BN;
    const int mBase = blockIdx.y * GM_BM;

    const __half* Wp = g_wh[proj];

    auto load_stage = [&](int stg, int kt2) {
        uint32_t base = sb + stg * (STAGE_WORDS * 4);
        #pragma unroll
        for (int sub = 0; sub < 2; sub++) {
            int k0 = kt2 * 64 + sub * 32;
            uint32_t sbase = base + sub * (SUB_WORDS * 4);
            #pragma unroll
            for (int i = 0; i < 2; i++) {
                int ch = tid + i * 256;
                int r = ch >> 2, c = ch & 3;
                cp16(sbase + (r * WSTRIDE + c * 4) * 4,
                     &g_xh[(size_t)(mBase + r) * D_MODEL + k0 + c * 8]);
            }
            #pragma unroll
            for (int i = 0; i < 4; i++) {
                int ch = tid + i * 256;
                int r = ch >> 2, c = ch & 3;
                cp16(sbase + ((A_SUB_WORDS + r * WSTRIDE + c * 4) * 4),
                     &Wp[(size_t)(nBase + r) * D_MODEL + k0 + c * 8]);
            }
        }
        CP_COMMIT();
    };

    float c[4][8][4];
    #pragma unroll
    for (int mt = 0; mt < 4; mt++)
        #pragma unroll
        for (int nt = 0; nt < 8; nt++)
            #pragma unroll
            for (int i = 0; i < 4; i++) c[mt][nt][i] = 0.f;

    load_stage(0, 0);
    load_stage(1, 1);

    for (int kt2 = 0; kt2 < GM_KT2; kt2++) {
        int stg = kt2 % NSTAGE;
        if (kt2 + 2 < GM_KT2) load_stage((kt2 + 2) % NSTAGE, kt2 + 2);
        if (kt2 < GM_KT2 - 2)       CP_WAIT(2);
        else if (kt2 == GM_KT2 - 2) CP_WAIT(1);
        else                        CP_WAIT(0);
        __syncthreads();

        #pragma unroll
        for (int sub = 0; sub < 2; sub++) {
            const uint32_t* sAw = smem + stg * STAGE_WORDS + sub * SUB_WORDS;
            const uint32_t* sBw = sAw + A_SUB_WORDS;

            // Two nt-halves; fp16 chain over the 2 k16 steps of this BK32 sub
            #pragma unroll
            for (int half = 0; half < 2; half++) {
                uint32_t hacc[4][4][2];
                #pragma unroll
                for (int ks = 0; ks < 2; ks++) {
                    const int kw = ks * 8 + tq;
                    uint32_t af[4][4], bf[4][2];
                    #pragma unroll
                    for (int mt = 0; mt < 4; mt++) {
                        int rb = (wr * 64 + mt * 16 + g) * WSTRIDE + kw;
                        af[mt][0] = sAw[rb];
                        af[mt][1] = sAw[rb + 8 * WSTRIDE];
                        af[mt][2] = sAw[rb + 4];
                        af[mt][3] = sAw[rb + 8 * WSTRIDE + 4];
                    }
                    #pragma unroll
                    for (int nth = 0; nth < 4; nth++) {
                        int nt = half * 4 + nth;
                        int rb = (wc * 64 + nt * 8 + g) * WSTRIDE + kw;
                        bf[nth][0] = sBw[rb];
                        bf[nth][1] = sBw[rb + 4];
                    }
                    #pragma unroll
                    for (int mt = 0; mt < 4; mt++)
                        #pragma unroll
                        for (int nth = 0; nth < 4; nth++) {
                            if (ks == 0) mma16h_z(hacc[mt][nth], af[mt], bf[nth]);
                            else         mma16h_a(hacc[mt][nth], af[mt], bf[nth]);
                        }
                }
                // Promote K=32 partial sums to fp32 masters
                #pragma unroll
                for (int mt = 0; mt < 4; mt++)
                    #pragma unroll
                    for (int nth = 0; nth < 4; nth++) {
                        int nt = half * 4 + nth;
                        float2 lo = __half22float2(*(__half2*)&hacc[mt][nth][0]);
                        float2 hi = __half22float2(*(__half2*)&hacc[mt][nth][1]);
                        c[mt][nt][0] += lo.x;
                        c[mt][nt][1] += lo.y;
                        c[mt][nt][2] += hi.x;
                        c[mt][nt][3] += hi.y;
                    }
            }
        }
        __syncthreads();
    }

    // Epilogue: bias add + store fp16
    const float* bp = (proj == 0) ? bq : (proj == 1) ? bk : bv;
    __half* outp    = (proj == 0) ? g_qh : (proj == 1) ? g_kh : g_vh;
    #pragma unroll
    for (int mt = 0; mt < 4; mt++) {
        #pragma unroll
        for (int nt = 0; nt < 8; nt++) {
            int row = mBase + wr * 64 + mt * 16 + g;
            int col = nBase + wc * 64 + nt * 8 + 2 * tq;
            float b0 = bp[col], b1 = bp[col + 1];
            __half2 h01 = __floats2half2_rn(c[mt][nt][0] + b0, c[mt][nt][1] + b1);
            __half2 h23 = __floats2half2_rn(c[mt][nt][2] + b0, c[mt][nt][3] + b1);
            *(__half2*)&outp[(size_t)row * D_MODEL + col] = h01;
            *(__half2*)&outp[(size_t)(row + 8) * D_MODEL + col] = h23;
        }
    }
}

// ---------------------------------------------------------------------------
// Attention + decay epilogue. fp16 smem, fp32 compute. Block per (b,h).
// sq/sv row stride 72 halves (36 words, 16B-alignable, conflict-free for
// their access patterns); sk stride 68 halves (<=2-way on k loads).
// ---------------------------------------------------------------------------
__global__ __launch_bounds__(128) void attn_kernel(
    const int* __restrict__ lenbuf, float* __restrict__ out)
{
    const int bh = blockIdx.x;
    const int b  = bh >> 4;
    const int h  = bh & 15;
    const int tid = threadIdx.x;

    __shared__ __align__(16) __half sq[SEQ][72];
    __shared__ __align__(16) __half sk[SEQ][68];
    __shared__ __align__(16) __half sv[SEQ][72];
    __shared__ float ssc[SEQ][24];
    __shared__ float sinv[SEQ];

    {
        size_t base = (size_t)(b * SEQ) * D_MODEL + h * DK;
        for (int e = tid; e < SEQ * (DK / 8); e += 128) {
            int s = e >> 3, c8 = (e & 7) * 8;
            size_t gi = base + (size_t)s * D_MODEL + c8;
            *(int4*)&sq[s][c8] = *(const int4*)&g_qh[gi];
            *(int4*)&sv[s][c8] = *(const int4*)&g_vh[gi];
            // sk row stride 68: 16B chunks may be 8B-aligned only
            uint2 kk0 = *(const uint2*)&g_kh[gi];
            uint2 kk1 = *(const uint2*)&g_kh[gi + 4];
            *(uint2*)&sk[s][c8]     = kk0;
            *(uint2*)&sk[s][c8 + 4] = kk1;
        }
    }
    __syncthreads();

    // length may be int64 or int32 (jax x64 config). All lengths >= 1,
    // so int32-view word 1 == 0 iff buffer is int64.
    bool is64 = (lenbuf[1] == 0);
    int len = is64 ? lenbuf[2 * b] : lenbuf[b];

    // Scores: 2x2 register tiles on threads 0..99, half2 loads
    if (tid < 100) {
        int i0 = (tid / 10) * 2, j0 = (tid % 10) * 2;
        float2 a00 = {0, 0}, a01 = {0, 0}, a10 = {0, 0}, a11 = {0, 0};
        #pragma unroll 8
        for (int d2 = 0; d2 < DK / 2; d2++) {
            float2 q0 = __half22float2(*(__half2*)&sq[i0][2 * d2]);
            float2 q1 = __half22float2(*(__half2*)&sq[i0 + 1][2 * d2]);
            float2 k0 = __half22float2(*(__half2*)&sk[j0][2 * d2]);
            float2 k1 = __half22float2(*(__half2*)&sk[j0 + 1][2 * d2]);
            a00.x += q0.x * k0.x; a00.y += q0.y * k0.y;
            a01.x += q0.x * k1.x; a01.y += q0.y * k1.y;
            a10.x += q1.x * k0.x; a10.y += q1.y * k0.y;
            a11.x += q1.x * k1.x; a11.y += q1.y * k1.y;
        }
        bool m0 = (j0 < len), m1 = (j0 + 1 < len);
        ssc[i0][j0]         = m0 ? __expf((a00.x + a00.y) * 0.125f) : 0.f;
        ssc[i0][j0 + 1]     = m1 ? __expf((a01.x + a01.y) * 0.125f) : 0.f;
        ssc[i0 + 1][j0]     = m0 ? __expf((a10.x + a10.y) * 0.125f) : 0.f;
        ssc[i0 + 1][j0 + 1] = m1 ? __expf((a11.x + a11.y) * 0.125f) : 0.f;
    }
    __syncthreads();

    if (tid < SEQ) {
        float s = 0.f;
        #pragma unroll
        for (int j = 0; j < SEQ; j++) s += ssc[tid][j];
        sinv[tid] = 1.f / (s + 1e-8f);
    }
    __syncthreads();

    // Output: 4 rows x 4 cols per thread on threads 0..79, half2 v loads
    if (tid < 80) {
        int i0 = (tid / 16) * 4;
        int d0 = (tid & 15) * 4;
        float s0 = sinv[i0], s1 = sinv[i0 + 1], s2 = sinv[i0 + 2], s3 = sinv[i0 + 3];
        float fi0 = (float)i0;
        float4 o0 = {0, 0, 0, 0}, o1 = {0, 0, 0, 0}, o2 = {0, 0, 0, 0}, o3 = {0, 0, 0, 0};
        float fj = 0.f;
        #pragma unroll
        for (int j = 0; j < SEQ; j++) {
            uint2 vr = *(const uint2*)&sv[j][d0];
            float2 va = __half22float2(*(__half2*)&vr.x);
            float2 vb = __half22float2(*(__half2*)&vr.y);
            float w0 = ssc[i0][j]     * s0 - fabsf(fi0 - fj);
            float w1 = ssc[i0 + 1][j] * s1 - fabsf(fi0 + 1.f - fj);
            float w2 = ssc[i0 + 2][j] * s2 - fabsf(fi0 + 2.f - fj);
            float w3 = ssc[i0 + 3][j] * s3 - fabsf(fi0 + 3.f - fj);
            o0.x += w0 * va.x; o0.y += w0 * va.y; o0.z += w0 * vb.x; o0.w += w0 * vb.y;
            o1.x += w1 * va.x; o1.y += w1 * va.y; o1.z += w1 * vb.x; o1.w += w1 * vb.y;
            o2.x += w2 * va.x; o2.y += w2 * va.y; o2.z += w2 * vb.x; o2.w += w2 * vb.y;
            o3.x += w3 * va.x; o3.y += w3 * va.y; o3.z += w3 * vb.x; o3.w += w3 * vb.y;
            fj += 1.f;
        }
        size_t base = (size_t)(b * SEQ + i0) * D_MODEL + h * DK + d0;
        *(float4*)&out[base]               = o0;
        *(float4*)&out[base + D_MODEL]     = o1;
        *(float4*)&out[base + 2 * D_MODEL] = o2;
        *(float4*)&out[base + 3 * D_MODEL] = o3;
    }
}

// ---------------------------------------------------------------------------
// Inputs (metadata order): Q, W_Q, b_Q, W_K, b_K, W_V, b_V, length
// ---------------------------------------------------------------------------
extern "C" void kernel_launch(void* const* d_in, const int* in_sizes, int n_in,
                              void* d_out, int out_size)
{
    const float* X  = (const float*)d_in[0];
    const float* Wq = (const float*)d_in[1];
    const float* bq = (const float*)d_in[2];
    const float* Wk = (const float*)d_in[3];
    const float* bk = (const float*)d_in[4];
    const float* Wv = (const float*)d_in[5];
    const float* bv = (const float*)d_in[6];
    const int*   ln = (const int*)d_in[7];

    __half* xh; cudaGetSymbolAddress((void**)&xh, g_xh);
    __half* wh; cudaGetSymbolAddress((void**)&wh, g_wh);

    {
        int n4 = M_TOTAL * D_MODEL / 4;
        int thr4 = (n4 + 3) / 4;
        f2h_kernel<<<(thr4 + 255) / 256, 256>>>(X, xh, n4);
        int w4 = D_MODEL * D_MODEL / 4;
        int wthr4 = (w4 + 3) / 4;
        f2h_kernel<<<(wthr4 + 255) / 256, 256>>>(Wq, wh + 0 * (size_t)D_MODEL * D_MODEL, w4);
        f2h_kernel<<<(wthr4 + 255) / 256, 256>>>(Wk, wh + 1 * (size_t)D_MODEL * D_MODEL, w4);
        f2h_kernel<<<(wthr4 + 255) / 256, 256>>>(Wv, wh + 2 * (size_t)D_MODEL * D_MODEL, w4);
    }

    cudaFuncSetAttribute(proj_gemm,
                         cudaFuncAttributeMaxDynamicSharedMemorySize, GM_SMEM_BYTES);

    dim3 grid(3 * (D_MODEL / GM_BN), M_TOTAL / GM_BM);   // (12, 320)
    proj_gemm<<<grid, 256, GM_SMEM_BYTES>>>(bq, bk, bv);

    attn_kernel<<<BATCH * NHEADS, 128>>>(ln, (float*)d_out);
}

// round 6
// speedup vs baseline: 1.0410x; 1.0410x over previous
#include <cuda_runtime.h>
#include <cuda_fp16.h>
#include <cstdint>
#include <math.h>

// Problem constants
#define D_MODEL 1024
#define NHEADS  16
#define DK      64
#define BATCH   2048
#define SEQ     20
#define M_TOTAL (BATCH * SEQ)   // 40960

// ---------------------------------------------------------------------------
// Scratch (fp16)
// ---------------------------------------------------------------------------
__device__ __half g_xh[(size_t)M_TOTAL * D_MODEL];
__device__ __half g_wh[3][(size_t)D_MODEL * D_MODEL];
__device__ __half g_qh[(size_t)M_TOTAL * D_MODEL];
__device__ __half g_kh[(size_t)M_TOTAL * D_MODEL];
__device__ __half g_vh[(size_t)M_TOTAL * D_MODEL];

// ---------------------------------------------------------------------------
// Merged fp32 -> fp16 conversion: X (10240 blocks) + 3 W (256 blocks each).
// 4 independent float4s per thread (MLP=4).
// ---------------------------------------------------------------------------
struct alignas(8) Half4 { __half2 a, b; };

#define XBLKS 10240
#define WBLKS 256

__global__ __launch_bounds__(256) void f2h_multi(
    const float* __restrict__ X,
    const float* __restrict__ Wq, const float* __restrict__ Wk, const float* __restrict__ Wv)
{
    __half* xh = g_xh;
    __half* wh = &g_wh[0][0];

    const float* src;
    __half* dst;
    int local;
    if (blockIdx.x < XBLKS) {
        src = X; dst = xh; local = blockIdx.x;
    } else {
        int w = (blockIdx.x - XBLKS) / WBLKS;
        local = (blockIdx.x - XBLKS) % WBLKS;
        src = (w == 0) ? Wq : (w == 1) ? Wk : Wv;
        dst = wh + (size_t)w * D_MODEL * D_MODEL;
    }
    int base = (local * 256 + threadIdx.x) * 4;   // exact fit, no bounds check
    float4 v[4];
    #pragma unroll
    for (int u = 0; u < 4; u++) v[u] = ((const float4*)src)[base + u];
    #pragma unroll
    for (int u = 0; u < 4; u++) {
        Half4 h;
        h.a = __floats2half2_rn(v[u].x, v[u].y);
        h.b = __floats2half2_rn(v[u].z, v[u].w);
        ((Half4*)dst)[base + u] = h;
    }
}

// ---------------------------------------------------------------------------
// fp16 m16n8k16 MMA, fp32 accumulate
// ---------------------------------------------------------------------------
__device__ __forceinline__ void mma16(float* c, const uint32_t* a, const uint32_t* b) {
    asm volatile(
        "mma.sync.aligned.m16n8k16.row.col.f32.f16.f16.f32 "
        "{%0,%1,%2,%3}, {%4,%5,%6,%7}, {%8,%9}, {%0,%1,%2,%3};"
        : "+f"(c[0]), "+f"(c[1]), "+f"(c[2]), "+f"(c[3])
        : "r"(a[0]), "r"(a[1]), "r"(a[2]), "r"(a[3]),
          "r"(b[0]), "r"(b[1]));
}

__device__ __forceinline__ void cp16(uint32_t saddr, const void* g) {
    asm volatile("cp.async.cg.shared.global [%0], [%1], 16;\n" :: "r"(saddr), "l"(g));
}
#define CP_COMMIT() asm volatile("cp.async.commit_group;\n" ::: "memory")
#define CP_WAIT(n)  asm volatile("cp.async.wait_group %0;\n" :: "n"(n) : "memory")

__device__ __forceinline__ uint32_t smem_u32(const void* p) {
    uint32_t a;
    asm("{ .reg .u64 t; cvta.to.shared.u64 t, %1; cvt.u32.u64 %0, t; }"
        : "=r"(a) : "l"(p));
    return a;
}

// ---------------------------------------------------------------------------
// Projection GEMM (R3 structure): Y = X @ W^T + b for Q/K/V, fp16 output.
// BM=128, BN=256, BK=32, 3-stage cp.async. 8 warps (2x4), warp tile 64x64.
// Smem rows 20-word stride: (g*20 + tq + {0,4}) mod 32 covers all banks.
// ---------------------------------------------------------------------------
#define GM_BM 128
#define GM_BN 256
#define GM_BK 32
#define WSTRIDE 20
#define A_STG_WORDS (GM_BM * WSTRIDE)     // 2560
#define B_STG_WORDS (GM_BN * WSTRIDE)     // 5120
#define STG_WORDS   (A_STG_WORDS + B_STG_WORDS)  // 7680
#define NSTAGE 3
#define GM_SMEM_BYTES (NSTAGE * STG_WORDS * 4)   // 92160
#define GM_KT (D_MODEL / GM_BK)           // 32

__global__ __launch_bounds__(256, 1) void proj_gemm(
    const float* __restrict__ bq, const float* __restrict__ bk, const float* __restrict__ bv)
{
    extern __shared__ uint32_t smem[];
    const uint32_t sb = smem_u32(smem);

    const int tid  = threadIdx.x;
    const int lane = tid & 31;
    const int warp = tid >> 5;
    const int wr   = warp >> 2;
    const int wc   = warp & 3;
    const int g    = lane >> 2;
    const int tq   = lane & 3;

    const int proj  = blockIdx.x >> 2;
    const int nBase = (blockIdx.x & 3) * GM_BN;
    const int mBase = blockIdx.y * GM_BM;

    const __half* Wp = g_wh[proj];

    auto load_stage = [&](int stg, int kt) {
        uint32_t base = sb + stg * (STG_WORDS * 4);
        int k0 = kt * GM_BK;
        #pragma unroll
        for (int i = 0; i < 2; i++) {
            int ch = tid + i * 256;
            int r = ch >> 2, c = ch & 3;
            cp16(base + (r * WSTRIDE + c * 4) * 4,
                 &g_xh[(size_t)(mBase + r) * D_MODEL + k0 + c * 8]);
        }
        #pragma unroll
        for (int i = 0; i < 4; i++) {
            int ch = tid + i * 256;
            int r = ch >> 2, c = ch & 3;
            cp16(base + (A_STG_WORDS + r * WSTRIDE + c * 4) * 4,
                 &Wp[(size_t)(nBase + r) * D_MODEL + k0 + c * 8]);
        }
        CP_COMMIT();
    };

    float c[4][8][4];
    #pragma unroll
    for (int mt = 0; mt < 4; mt++)
        #pragma unroll
        for (int nt = 0; nt < 8; nt++)
            #pragma unroll
            for (int i = 0; i < 4; i++) c[mt][nt][i] = 0.f;

    load_stage(0, 0);
    load_stage(1, 1);

    for (int kt = 0; kt < GM_KT; kt++) {
        int stg = kt % NSTAGE;
        if (kt + 2 < GM_KT) load_stage((kt + 2) % NSTAGE, kt + 2);
        if (kt < GM_KT - 2)      CP_WAIT(2);
        else if (kt == GM_KT - 2) CP_WAIT(1);
        else                      CP_WAIT(0);
        __syncthreads();

        const uint32_t* sAw = smem + stg * STG_WORDS;
        const uint32_t* sBw = sAw + A_STG_WORDS;

        #pragma unroll
        for (int ks = 0; ks < 2; ks++) {
            const int kw = ks * 8 + tq;
            uint32_t af[4][4], bf[8][2];
            #pragma unroll
            for (int mt = 0; mt < 4; mt++) {
                int rb = (wr * 64 + mt * 16 + g) * WSTRIDE + kw;
                af[mt][0] = sAw[rb];
                af[mt][1] = sAw[rb + 8 * WSTRIDE];
                af[mt][2] = sAw[rb + 4];
                af[mt][3] = sAw[rb + 8 * WSTRIDE + 4];
            }
            #pragma unroll
            for (int nt = 0; nt < 8; nt++) {
                int rb = (wc * 64 + nt * 8 + g) * WSTRIDE + kw;
                bf[nt][0] = sBw[rb];
                bf[nt][1] = sBw[rb + 4];
            }
            #pragma unroll
            for (int mt = 0; mt < 4; mt++)
                #pragma unroll
                for (int nt = 0; nt < 8; nt++)
                    mma16(c[mt][nt], af[mt], bf[nt]);
        }
        __syncthreads();
    }

    // Epilogue: bias add + store fp16
    const float* bp = (proj == 0) ? bq : (proj == 1) ? bk : bv;
    __half* outp    = (proj == 0) ? g_qh : (proj == 1) ? g_kh : g_vh;
    #pragma unroll
    for (int mt = 0; mt < 4; mt++) {
        #pragma unroll
        for (int nt = 0; nt < 8; nt++) {
            int row = mBase + wr * 64 + mt * 16 + g;
            int col = nBase + wc * 64 + nt * 8 + 2 * tq;
            float b0 = bp[col], b1 = bp[col + 1];
            __half2 h01 = __floats2half2_rn(c[mt][nt][0] + b0, c[mt][nt][1] + b1);
            __half2 h23 = __floats2half2_rn(c[mt][nt][2] + b0, c[mt][nt][3] + b1);
            *(__half2*)&outp[(size_t)row * D_MODEL + col] = h01;
            *(__half2*)&outp[(size_t)(row + 8) * D_MODEL + col] = h23;
        }
    }
}

// ---------------------------------------------------------------------------
// Attention + decay. fp16 gmem -> fp32 smem (cvt once at load).
// Weight matrix wgtT[j][i] = ssc[i][j]*sinv[i] - |i-j| precomputed in smem.
// Block per (b,h), 128 threads.
// ---------------------------------------------------------------------------
__global__ __launch_bounds__(128) void attn_kernel(
    const int* __restrict__ lenbuf, float* __restrict__ out)
{
    const int bh = blockIdx.x;
    const int b  = bh >> 4;
    const int h  = bh & 15;
    const int tid = threadIdx.x;

    __shared__ __align__(16) float sq[SEQ][68];
    __shared__ __align__(16) float sk[SEQ][68];
    __shared__ __align__(16) float sv[SEQ][68];
    __shared__ float ssc[SEQ][24];
    __shared__ float sinv[SEQ];
    __shared__ __align__(16) float wgtT[SEQ][24];   // [j][i]

    {
        size_t base = (size_t)(b * SEQ) * D_MODEL + h * DK;
        for (int e = tid; e < SEQ * (DK / 8); e += 128) {
            int s = e >> 3, d8 = (e & 7) * 8;
            size_t gi = base + (size_t)s * D_MODEL + d8;
            Half4 q0 = *(const Half4*)&g_qh[gi];
            Half4 q1 = *(const Half4*)&g_qh[gi + 4];
            Half4 k0 = *(const Half4*)&g_kh[gi];
            Half4 k1 = *(const Half4*)&g_kh[gi + 4];
            Half4 v0 = *(const Half4*)&g_vh[gi];
            Half4 v1 = *(const Half4*)&g_vh[gi + 4];
            float2 f;
            f = __half22float2(q0.a); sq[s][d8 + 0] = f.x; sq[s][d8 + 1] = f.y;
            f = __half22float2(q0.b); sq[s][d8 + 2] = f.x; sq[s][d8 + 3] = f.y;
            f = __half22float2(q1.a); sq[s][d8 + 4] = f.x; sq[s][d8 + 5] = f.y;
            f = __half22float2(q1.b); sq[s][d8 + 6] = f.x; sq[s][d8 + 7] = f.y;
            f = __half22float2(k0.a); sk[s][d8 + 0] = f.x; sk[s][d8 + 1] = f.y;
            f = __half22float2(k0.b); sk[s][d8 + 2] = f.x; sk[s][d8 + 3] = f.y;
            f = __half22float2(k1.a); sk[s][d8 + 4] = f.x; sk[s][d8 + 5] = f.y;
            f = __half22float2(k1.b); sk[s][d8 + 6] = f.x; sk[s][d8 + 7] = f.y;
            f = __half22float2(v0.a); sv[s][d8 + 0] = f.x; sv[s][d8 + 1] = f.y;
            f = __half22float2(v0.b); sv[s][d8 + 2] = f.x; sv[s][d8 + 3] = f.y;
            f = __half22float2(v1.a); sv[s][d8 + 4] = f.x; sv[s][d8 + 5] = f.y;
            f = __half22float2(v1.b); sv[s][d8 + 6] = f.x; sv[s][d8 + 7] = f.y;
        }
    }
    __syncthreads();

    // length may be int64 or int32 (jax x64 config). All lengths >= 1,
    // so int32-view word 1 == 0 iff buffer is int64.
    bool is64 = (lenbuf[1] == 0);
    int len = is64 ? lenbuf[2 * b] : lenbuf[b];

    // Scores: 2x2 register tiles on threads 0..99, float4 loads
    if (tid < 100) {
        int i0 = (tid / 10) * 2, j0 = (tid % 10) * 2;
        float a00 = 0.f, a01 = 0.f, a10 = 0.f, a11 = 0.f;
        #pragma unroll
        for (int d4 = 0; d4 < DK / 4; d4++) {
            float4 q0 = *(const float4*)&sq[i0][4 * d4];
            float4 q1 = *(const float4*)&sq[i0 + 1][4 * d4];
            float4 k0 = *(const float4*)&sk[j0][4 * d4];
            float4 k1 = *(const float4*)&sk[j0 + 1][4 * d4];
            a00 += q0.x * k0.x + q0.y * k0.y + q0.z * k0.z + q0.w * k0.w;
            a01 += q0.x * k1.x + q0.y * k1.y + q0.z * k1.z + q0.w * k1.w;
            a10 += q1.x * k0.x + q1.y * k0.y + q1.z * k0.z + q1.w * k0.w;
            a11 += q1.x * k1.x + q1.y * k1.y + q1.z * k1.z + q1.w * k1.w;
        }
        bool m0 = (j0 < len), m1 = (j0 + 1 < len);
        ssc[i0][j0]         = m0 ? __expf(a00 * 0.125f) : 0.f;
        ssc[i0][j0 + 1]     = m1 ? __expf(a01 * 0.125f) : 0.f;
        ssc[i0 + 1][j0]     = m0 ? __expf(a10 * 0.125f) : 0.f;
        ssc[i0 + 1][j0 + 1] = m1 ? __expf(a11 * 0.125f) : 0.f;
    }
    __syncthreads();

    if (tid < SEQ) {
        float s = 0.f;
        #pragma unroll
        for (int j = 0; j < SEQ; j++) s += ssc[tid][j];
        sinv[tid] = 1.f / (s + 1e-8f);
    }
    __syncthreads();

    // Fill wgtT[j][i] = ssc[i][j]*sinv[i] - |i-j|  (400 elements)
    for (int e = tid; e < SEQ * SEQ; e += 128) {
        int i = e % SEQ, j = e / SEQ;
        wgtT[j][i] = ssc[i][j] * sinv[i] - (float)((i > j) ? (i - j) : (j - i));
    }
    __syncthreads();

    // Output: 4 rows x 4 cols per thread on threads 0..79
    if (tid < 80) {
        int i0 = (tid / 16) * 4;
        int d0 = (tid & 15) * 4;
        float4 o0 = {0, 0, 0, 0}, o1 = {0, 0, 0, 0}, o2 = {0, 0, 0, 0}, o3 = {0, 0, 0, 0};
        #pragma unroll
        for (int j = 0; j < SEQ; j++) {
            float4 vv = *(const float4*)&sv[j][d0];
            float4 w  = *(const float4*)&wgtT[j][i0];
            o0.x += w.x * vv.x; o0.y += w.x * vv.y; o0.z += w.x * vv.z; o0.w += w.x * vv.w;
            o1.x += w.y * vv.x; o1.y += w.y * vv.y; o1.z += w.y * vv.z; o1.w += w.y * vv.w;
            o2.x += w.z * vv.x; o2.y += w.z * vv.y; o2.z += w.z * vv.z; o2.w += w.z * vv.w;
            o3.x += w.w * vv.x; o3.y += w.w * vv.y; o3.z += w.w * vv.z; o3.w += w.w * vv.w;
        }
        size_t base = (size_t)(b * SEQ + i0) * D_MODEL + h * DK + d0;
        *(float4*)&out[base]               = o0;
        *(float4*)&out[base + D_MODEL]     = o1;
        *(float4*)&out[base + 2 * D_MODEL] = o2;
        *(float4*)&out[base + 3 * D_MODEL] = o3;
    }
}

// ---------------------------------------------------------------------------
// Inputs (metadata order): Q, W_Q, b_Q, W_K, b_K, W_V, b_V, length
// ---------------------------------------------------------------------------
extern "C" void kernel_launch(void* const* d_in, const int* in_sizes, int n_in,
                              void* d_out, int out_size)
{
    const float* X  = (const float*)d_in[0];
    const float* Wq = (const float*)d_in[1];
    const float* bq = (const float*)d_in[2];
    const float* Wk = (const float*)d_in[3];
    const float* bk = (const float*)d_in[4];
    const float* Wv = (const float*)d_in[5];
    const float* bv = (const float*)d_in[6];
    const int*   ln = (const int*)d_in[7];

    f2h_multi<<<XBLKS + 3 * WBLKS, 256>>>(X, Wq, Wk, Wv);

    cudaFuncSetAttribute(proj_gemm,
                         cudaFuncAttributeMaxDynamicSharedMemorySize, GM_SMEM_BYTES);

    // grid.x fastest = (proj, n-tile): X m-tile reused 12x from L2, W resident
    dim3 grid(3 * (D_MODEL / GM_BN), M_TOTAL / GM_BM);   // (12, 320)
    proj_gemm<<<grid, 256, GM_SMEM_BYTES>>>(bq, bk, bv);

    attn_kernel<<<BATCH * NHEADS, 128>>>(ln, (float*)d_out);
}

// round 7
// speedup vs baseline: 1.1317x; 1.0872x over previous
#include <cuda_runtime.h>
#include <cuda_fp16.h>
#include <cstdint>
#include <math.h>

// Problem constants
#define D_MODEL 1024
#define NHEADS  16
#define DK      64
#define BATCH   2048
#define SEQ     20
#define M_TOTAL (BATCH * SEQ)   // 40960

// ---------------------------------------------------------------------------
// Scratch (fp16)
// ---------------------------------------------------------------------------
__device__ __half g_xh[(size_t)M_TOTAL * D_MODEL];
__device__ __half g_wh[3][(size_t)D_MODEL * D_MODEL];
__device__ __half g_qh[(size_t)M_TOTAL * D_MODEL];
__device__ __half g_kh[(size_t)M_TOTAL * D_MODEL];
__device__ __half g_vh[(size_t)M_TOTAL * D_MODEL];

// ---------------------------------------------------------------------------
// Merged fp32 -> fp16 conversion with streaming 16B stores.
// Each thread: 4x float4 loads (ldcs) -> 2x 16B stores (stcs).
// X: 40960*1024 floats = 5242880 8-float chunks -> 10240 blocks of 256 thr x 2
// W: each 1024*1024 floats = 131072 chunks -> 256 blocks each
// ---------------------------------------------------------------------------
struct alignas(16) Half8 { __half2 a, b, c, d; };

#define XBLKS 10240
#define WBLKS 256

__global__ __launch_bounds__(256) void f2h_multi(
    const float* __restrict__ X,
    const float* __restrict__ Wq, const float* __restrict__ Wk, const float* __restrict__ Wv)
{
    const float* src;
    __half* dst;
    int local;
    if (blockIdx.x < XBLKS) {
        src = X; dst = g_xh; local = blockIdx.x;
    } else {
        int w = (blockIdx.x - XBLKS) / WBLKS;
        local = (blockIdx.x - XBLKS) % WBLKS;
        src = (w == 0) ? Wq : (w == 1) ? Wk : Wv;
        dst = &g_wh[w][0];
    }
    // chunk = 8 floats -> 1 Half8. Thread handles chunks 2t, 2t+1.
    int c0 = (local * 256 + threadIdx.x) * 2;    // exact fit
    float4 v[4];
    #pragma unroll
    for (int u = 0; u < 4; u++)
        v[u] = __ldcs(&((const float4*)src)[c0 * 2 + u]);
    #pragma unroll
    for (int u = 0; u < 2; u++) {
        Half8 h;
        h.a = __floats2half2_rn(v[2 * u].x,     v[2 * u].y);
        h.b = __floats2half2_rn(v[2 * u].z,     v[2 * u].w);
        h.c = __floats2half2_rn(v[2 * u + 1].x, v[2 * u + 1].y);
        h.d = __floats2half2_rn(v[2 * u + 1].z, v[2 * u + 1].w);
        __stcs((float4*)&((Half8*)dst)[c0 + u], *(float4*)&h);
    }
}

// ---------------------------------------------------------------------------
// fp16 m16n8k16 MMA, fp32 accumulate
// ---------------------------------------------------------------------------
__device__ __forceinline__ void mma16(float* c, const uint32_t* a, const uint32_t* b) {
    asm volatile(
        "mma.sync.aligned.m16n8k16.row.col.f32.f16.f16.f32 "
        "{%0,%1,%2,%3}, {%4,%5,%6,%7}, {%8,%9}, {%0,%1,%2,%3};"
        : "+f"(c[0]), "+f"(c[1]), "+f"(c[2]), "+f"(c[3])
        : "r"(a[0]), "r"(a[1]), "r"(a[2]), "r"(a[3]),
          "r"(b[0]), "r"(b[1]));
}

__device__ __forceinline__ void cp16(uint32_t saddr, const void* g) {
    asm volatile("cp.async.cg.shared.global [%0], [%1], 16;\n" :: "r"(saddr), "l"(g));
}
#define CP_COMMIT() asm volatile("cp.async.commit_group;\n" ::: "memory")
#define CP_WAIT(n)  asm volatile("cp.async.wait_group %0;\n" :: "n"(n) : "memory")

__device__ __forceinline__ uint32_t smem_u32(const void* p) {
    uint32_t a;
    asm("{ .reg .u64 t; cvta.to.shared.u64 t, %1; cvt.u32.u64 %0, t; }"
        : "=r"(a) : "l"(p));
    return a;
}

// ---------------------------------------------------------------------------
// Projection GEMM: Y = X @ W^T + b, fp16 output. 2 CTAs/SM.
// BM=128, BN=128, BK=32, 3-stage cp.async. 8 warps (2x4), warp tile 64x32.
// Smem rows 20-word stride: (g*20 + tq + {0,4}) mod 32 covers all banks.
// ---------------------------------------------------------------------------
#define GM_BM 128
#define GM_BN 128
#define GM_BK 32
#define WSTRIDE 20
#define A_STG_WORDS (GM_BM * WSTRIDE)     // 2560
#define B_STG_WORDS (GM_BN * WSTRIDE)     // 2560
#define STG_WORDS   (A_STG_WORDS + B_STG_WORDS)  // 5120
#define NSTAGE 3
#define GM_SMEM_BYTES (NSTAGE * STG_WORDS * 4)   // 61440
#define GM_KT (D_MODEL / GM_BK)           // 32

__global__ __launch_bounds__(256, 2) void proj_gemm(
    const float* __restrict__ bq, const float* __restrict__ bk, const float* __restrict__ bv)
{
    extern __shared__ uint32_t smem[];
    const uint32_t sb = smem_u32(smem);

    const int tid  = threadIdx.x;
    const int lane = tid & 31;
    const int warp = tid >> 5;
    const int wr   = warp >> 2;     // 0..1
    const int wc   = warp & 3;      // 0..3
    const int g    = lane >> 2;
    const int tq   = lane & 3;

    const int proj  = blockIdx.x >> 3;              // 0..2
    const int nBase = (blockIdx.x & 7) * GM_BN;     // 0..896
    const int mBase = blockIdx.y * GM_BM;

    const __half* Wp = g_wh[proj];

    auto load_stage = [&](int stg, int kt) {
        uint32_t base = sb + stg * (STG_WORDS * 4);
        int k0 = kt * GM_BK;
        #pragma unroll
        for (int i = 0; i < 2; i++) {
            int ch = tid + i * 256;       // 0..511
            int r = ch >> 2, c = ch & 3;
            cp16(base + (r * WSTRIDE + c * 4) * 4,
                 &g_xh[(size_t)(mBase + r) * D_MODEL + k0 + c * 8]);
        }
        #pragma unroll
        for (int i = 0; i < 2; i++) {
            int ch = tid + i * 256;
            int r = ch >> 2, c = ch & 3;
            cp16(base + (A_STG_WORDS + r * WSTRIDE + c * 4) * 4,
                 &Wp[(size_t)(nBase + r) * D_MODEL + k0 + c * 8]);
        }
        CP_COMMIT();
    };

    float c[4][4][4];
    #pragma unroll
    for (int mt = 0; mt < 4; mt++)
        #pragma unroll
        for (int nt = 0; nt < 4; nt++)
            #pragma unroll
            for (int i = 0; i < 4; i++) c[mt][nt][i] = 0.f;

    load_stage(0, 0);
    load_stage(1, 1);

    for (int kt = 0; kt < GM_KT; kt++) {
        int stg = kt % NSTAGE;
        if (kt + 2 < GM_KT) load_stage((kt + 2) % NSTAGE, kt + 2);
        if (kt < GM_KT - 2)      CP_WAIT(2);
        else if (kt == GM_KT - 2) CP_WAIT(1);
        else                      CP_WAIT(0);
        __syncthreads();

        const uint32_t* sAw = smem + stg * STG_WORDS;
        const uint32_t* sBw = sAw + A_STG_WORDS;

        #pragma unroll
        for (int ks = 0; ks < 2; ks++) {
            const int kw = ks * 8 + tq;
            uint32_t af[4][4], bf[4][2];
            #pragma unroll
            for (int mt = 0; mt < 4; mt++) {
                int rb = (wr * 64 + mt * 16 + g) * WSTRIDE + kw;
                af[mt][0] = sAw[rb];
                af[mt][1] = sAw[rb + 8 * WSTRIDE];
                af[mt][2] = sAw[rb + 4];
                af[mt][3] = sAw[rb + 8 * WSTRIDE + 4];
            }
            #pragma unroll
            for (int nt = 0; nt < 4; nt++) {
                int rb = (wc * 32 + nt * 8 + g) * WSTRIDE + kw;
                bf[nt][0] = sBw[rb];
                bf[nt][1] = sBw[rb + 4];
            }
            #pragma unroll
            for (int mt = 0; mt < 4; mt++)
                #pragma unroll
                for (int nt = 0; nt < 4; nt++)
                    mma16(c[mt][nt], af[mt], bf[nt]);
        }
        __syncthreads();
    }

    // Epilogue: bias add + store fp16
    const float* bp = (proj == 0) ? bq : (proj == 1) ? bk : bv;
    __half* outp    = (proj == 0) ? g_qh : (proj == 1) ? g_kh : g_vh;
    #pragma unroll
    for (int mt = 0; mt < 4; mt++) {
        #pragma unroll
        for (int nt = 0; nt < 4; nt++) {
            int row = mBase + wr * 64 + mt * 16 + g;
            int col = nBase + wc * 32 + nt * 8 + 2 * tq;
            float b0 = bp[col], b1 = bp[col + 1];
            __half2 h01 = __floats2half2_rn(c[mt][nt][0] + b0, c[mt][nt][1] + b1);
            __half2 h23 = __floats2half2_rn(c[mt][nt][2] + b0, c[mt][nt][3] + b1);
            *(__half2*)&outp[(size_t)row * D_MODEL + col] = h01;
            *(__half2*)&outp[(size_t)(row + 8) * D_MODEL + col] = h23;
        }
    }
}

// ---------------------------------------------------------------------------
// Attention + decay. fp16 gmem -> fp32 smem (cvt once at load).
// wgtT[j][i] = ssc[i][j]*sinv[i] - |i-j| precomputed. Block per (b,h).
// ---------------------------------------------------------------------------
struct alignas(8) Half4 { __half2 a, b; };

__global__ __launch_bounds__(128) void attn_kernel(
    const int* __restrict__ lenbuf, float* __restrict__ out)
{
    const int bh = blockIdx.x;
    const int b  = bh >> 4;
    const int h  = bh & 15;
    const int tid = threadIdx.x;

    __shared__ __align__(16) float sq[SEQ][68];
    __shared__ __align__(16) float sk[SEQ][68];
    __shared__ __align__(16) float sv[SEQ][68];
    __shared__ float ssc[SEQ][24];
    __shared__ float sinv[SEQ];
    __shared__ __align__(16) float wgtT[SEQ][24];   // [j][i]

    {
        size_t base = (size_t)(b * SEQ) * D_MODEL + h * DK;
        for (int e = tid; e < SEQ * (DK / 8); e += 128) {
            int s = e >> 3, d8 = (e & 7) * 8;
            size_t gi = base + (size_t)s * D_MODEL + d8;
            Half4 q0 = *(const Half4*)&g_qh[gi];
            Half4 q1 = *(const Half4*)&g_qh[gi + 4];
            Half4 k0 = *(const Half4*)&g_kh[gi];
            Half4 k1 = *(const Half4*)&g_kh[gi + 4];
            Half4 v0 = *(const Half4*)&g_vh[gi];
            Half4 v1 = *(const Half4*)&g_vh[gi + 4];
            float2 f;
            f = __half22float2(q0.a); sq[s][d8 + 0] = f.x; sq[s][d8 + 1] = f.y;
            f = __half22float2(q0.b); sq[s][d8 + 2] = f.x; sq[s][d8 + 3] = f.y;
            f = __half22float2(q1.a); sq[s][d8 + 4] = f.x; sq[s][d8 + 5] = f.y;
            f = __half22float2(q1.b); sq[s][d8 + 6] = f.x; sq[s][d8 + 7] = f.y;
            f = __half22float2(k0.a); sk[s][d8 + 0] = f.x; sk[s][d8 + 1] = f.y;
            f = __half22float2(k0.b); sk[s][d8 + 2] = f.x; sk[s][d8 + 3] = f.y;
            f = __half22float2(k1.a); sk[s][d8 + 4] = f.x; sk[s][d8 + 5] = f.y;
            f = __half22float2(k1.b); sk[s][d8 + 6] = f.x; sk[s][d8 + 7] = f.y;
            f = __half22float2(v0.a); sv[s][d8 + 0] = f.x; sv[s][d8 + 1] = f.y;
            f = __half22float2(v0.b); sv[s][d8 + 2] = f.x; sv[s][d8 + 3] = f.y;
            f = __half22float2(v1.a); sv[s][d8 + 4] = f.x; sv[s][d8 + 5] = f.y;
            f = __half22float2(v1.b); sv[s][d8 + 6] = f.x; sv[s][d8 + 7] = f.y;
        }
    }
    __syncthreads();

    // length may be int64 or int32 (jax x64 config). All lengths >= 1,
    // so int32-view word 1 == 0 iff buffer is int64.
    bool is64 = (lenbuf[1] == 0);
    int len = is64 ? lenbuf[2 * b] : lenbuf[b];

    // Scores: 2x2 register tiles on threads 0..99, float4 loads
    if (tid < 100) {
        int i0 = (tid / 10) * 2, j0 = (tid % 10) * 2;
        float a00 = 0.f, a01 = 0.f, a10 = 0.f, a11 = 0.f;
        #pragma unroll
        for (int d4 = 0; d4 < DK / 4; d4++) {
            float4 q0 = *(const float4*)&sq[i0][4 * d4];
            float4 q1 = *(const float4*)&sq[i0 + 1][4 * d4];
            float4 k0 = *(const float4*)&sk[j0][4 * d4];
            float4 k1 = *(const float4*)&sk[j0 + 1][4 * d4];
            a00 += q0.x * k0.x + q0.y * k0.y + q0.z * k0.z + q0.w * k0.w;
            a01 += q0.x * k1.x + q0.y * k1.y + q0.z * k1.z + q0.w * k1.w;
            a10 += q1.x * k0.x + q1.y * k0.y + q1.z * k0.z + q1.w * k0.w;
            a11 += q1.x * k1.x + q1.y * k1.y + q1.z * k1.z + q1.w * k1.w;
        }
        bool m0 = (j0 < len), m1 = (j0 + 1 < len);
        ssc[i0][j0]         = m0 ? __expf(a00 * 0.125f) : 0.f;
        ssc[i0][j0 + 1]     = m1 ? __expf(a01 * 0.125f) : 0.f;
        ssc[i0 + 1][j0]     = m0 ? __expf(a10 * 0.125f) : 0.f;
        ssc[i0 + 1][j0 + 1] = m1 ? __expf(a11 * 0.125f) : 0.f;
    }
    __syncthreads();

    if (tid < SEQ) {
        float s = 0.f;
        #pragma unroll
        for (int j = 0; j < SEQ; j++) s += ssc[tid][j];
        sinv[tid] = 1.f / (s + 1e-8f);
    }
    __syncthreads();

    for (int e = tid; e < SEQ * SEQ; e += 128) {
        int i = e % SEQ, j = e / SEQ;
        wgtT[j][i] = ssc[i][j] * sinv[i] - (float)((i > j) ? (i - j) : (j - i));
    }
    __syncthreads();

    // Output: 4 rows x 4 cols per thread on threads 0..79
    if (tid < 80) {
        int i0 = (tid / 16) * 4;
        int d0 = (tid & 15) * 4;
        float4 o0 = {0, 0, 0, 0}, o1 = {0, 0, 0, 0}, o2 = {0, 0, 0, 0}, o3 = {0, 0, 0, 0};
        #pragma unroll
        for (int j = 0; j < SEQ; j++) {
            float4 vv = *(const float4*)&sv[j][d0];
            float4 w  = *(const float4*)&wgtT[j][i0];
            o0.x += w.x * vv.x; o0.y += w.x * vv.y; o0.z += w.x * vv.z; o0.w += w.x * vv.w;
            o1.x += w.y * vv.x; o1.y += w.y * vv.y; o1.z += w.y * vv.z; o1.w += w.y * vv.w;
            o2.x += w.z * vv.x; o2.y += w.z * vv.y; o2.z += w.z * vv.z; o2.w += w.z * vv.w;
            o3.x += w.w * vv.x; o3.y += w.w * vv.y; o3.z += w.w * vv.z; o3.w += w.w * vv.w;
        }
        size_t base = (size_t)(b * SEQ + i0) * D_MODEL + h * DK + d0;
        *(float4*)&out[base]               = o0;
        *(float4*)&out[base + D_MODEL]     = o1;
        *(float4*)&out[base + 2 * D_MODEL] = o2;
        *(float4*)&out[base + 3 * D_MODEL] = o3;
    }
}

// ---------------------------------------------------------------------------
// Inputs (metadata order): Q, W_Q, b_Q, W_K, b_K, W_V, b_V, length
// ---------------------------------------------------------------------------
extern "C" void kernel_launch(void* const* d_in, const int* in_sizes, int n_in,
                              void* d_out, int out_size)
{
    const float* X  = (const float*)d_in[0];
    const float* Wq = (const float*)d_in[1];
    const float* bq = (const float*)d_in[2];
    const float* Wk = (const float*)d_in[3];
    const float* bk = (const float*)d_in[4];
    const float* Wv = (const float*)d_in[5];
    const float* bv = (const float*)d_in[6];
    const int*   ln = (const int*)d_in[7];

    f2h_multi<<<XBLKS + 3 * WBLKS, 256>>>(X, Wq, Wk, Wv);

    cudaFuncSetAttribute(proj_gemm,
                         cudaFuncAttributeMaxDynamicSharedMemorySize, GM_SMEM_BYTES);

    // grid.x fastest = (proj, n-tile): X m-tile reused 24x from L2, W resident
    dim3 grid(3 * (D_MODEL / GM_BN), M_TOTAL / GM_BM);   // (24, 320)
    proj_gemm<<<grid, 256, GM_SMEM_BYTES>>>(bq, bk, bv);

    attn_kernel<<<BATCH * NHEADS, 128>>>(ln, (float*)d_out);
}